// round 1
// baseline (speedup 1.0000x reference)
#include <cuda_runtime.h>
#include <math.h>

// Problem constants
#define Bn   8
#define Hh   56
#define Ww   56
#define Cc   512
#define C2   256
#define HW   3136           // 56*56
#define BHW  25088          // 8*3136
#define NHh  8
#define Dd   32             // C/NH/2

// ---------------------------------------------------------------------------
// Scratch (device globals; no allocation in kernel_launch per harness rules)
// ---------------------------------------------------------------------------
__device__ float g_xn   [BHW * Cc];          // LN(x)
__device__ float g_xen  [BHW * Cc];          // LN(x_e)
__device__ float g_bfeat[BHW * Cc];          // gelu(xn @ l_w)
__device__ float g_kv   [BHW * Cc];          // bfeat @ kv_w  (k = [:256], v = [256:])
__device__ float g_xcat [BHW * Cc];          // [attn_up | cutted*e]
__device__ float g_cut  [BHW * C2];          // xn @ qcut_w
__device__ float g_e1   [BHW * C2];          // xen @ efore_w
__device__ float g_e2   [BHW * C2];          // depthwise conv out
__device__ float g_pool [Bn * 49 * 1024];    // pooled concat(xn,xen)
__device__ float g_m    [Bn * 49 * C2];      // pooled @ sc_w
__device__ float g_sc   [Bn * NHh * 49 * HW];// scores / probs
__device__ float g_a49  [Bn * NHh * 49 * Dd];// attn @ v

// ---------------------------------------------------------------------------
// LayerNorm: one block (128 thr) per pixel; first 25088 blocks = x, rest = x_e
// ---------------------------------------------------------------------------
__global__ void ln_kernel(const float* __restrict__ x, const float* __restrict__ xe,
                          const float* __restrict__ nw, const float* __restrict__ nb,
                          const float* __restrict__ ew, const float* __restrict__ eb)
{
    int p   = blockIdx.x;
    int tid = threadIdx.x;                 // 128
    bool sec = p >= BHW;
    int pix  = sec ? p - BHW : p;
    const float* src = (sec ? xe : x) + (size_t)pix * Cc;
    float*       dst = (sec ? g_xen : g_xn) + (size_t)pix * Cc;
    const float* w   = sec ? ew : nw;
    const float* bb  = sec ? eb : nb;

    float4 v = *(const float4*)(src + tid * 4);
    float s  = v.x + v.y + v.z + v.w;
    float ss = v.x*v.x + v.y*v.y + v.z*v.z + v.w*v.w;
    #pragma unroll
    for (int o = 16; o > 0; o >>= 1) {
        s  += __shfl_xor_sync(0xffffffffu, s,  o);
        ss += __shfl_xor_sync(0xffffffffu, ss, o);
    }
    __shared__ float sm[4], sm2[4];
    int wid = tid >> 5;
    if ((tid & 31) == 0) { sm[wid] = s; sm2[wid] = ss; }
    __syncthreads();
    s  = sm[0] + sm[1] + sm[2] + sm[3];
    ss = sm2[0] + sm2[1] + sm2[2] + sm2[3];

    float mu  = s * (1.0f / Cc);
    float var = ss * (1.0f / Cc) - mu * mu;
    float inv = rsqrtf(var + 1e-6f);

    float4 wv = *(const float4*)(w  + tid * 4);
    float4 bv = *(const float4*)(bb + tid * 4);
    float4 o;
    o.x = (v.x - mu) * inv * wv.x + bv.x;
    o.y = (v.y - mu) * inv * wv.y + bv.y;
    o.z = (v.z - mu) * inv * wv.z + bv.z;
    o.w = (v.w - mu) * inv * wv.w + bv.w;
    *(float4*)(dst + tid * 4) = o;
}

// ---------------------------------------------------------------------------
// Pool: mean over 8x8 blocks of concat(xn,xen). block = (b,pi,pj), 256 threads
// (4 channels each of the 1024 concat channels)
// ---------------------------------------------------------------------------
__global__ void pool_kernel()
{
    int blk = blockIdx.x;                  // b*49 + pi*7 + pj
    int b  = blk / 49;
    int pp = blk % 49;
    int pi = pp / 7, pj = pp % 7;
    int c4 = threadIdx.x * 4;

    const float* src = (c4 < Cc) ? g_xn : g_xen;
    int cc = (c4 < Cc) ? c4 : c4 - Cc;

    float4 s = make_float4(0.f, 0.f, 0.f, 0.f);
    for (int ii = 0; ii < 8; ii++)
        for (int jj = 0; jj < 8; jj++) {
            int pix = b * HW + (pi * 8 + ii) * Ww + (pj * 8 + jj);
            float4 v = *(const float4*)(src + (size_t)pix * Cc + cc);
            s.x += v.x; s.y += v.y; s.z += v.z; s.w += v.w;
        }
    const float inv = 1.0f / 64.0f;
    float4 o = make_float4(s.x * inv, s.y * inv, s.z * inv, s.w * inv);
    *(float4*)(g_pool + (size_t)blk * 1024 + c4) = o;
}

// ---------------------------------------------------------------------------
// m = pooled @ sc_w + sc_b.  Block handles 8 of the 392 rows; 256 thr = 256 outs
// ---------------------------------------------------------------------------
__global__ void mproj_kernel(const float* __restrict__ sw, const float* __restrict__ sb)
{
    __shared__ float ps[8 * 1024];
    int r0  = blockIdx.x * 8;
    int tid = threadIdx.x;
    for (int i = tid * 4; i < 8 * 1024; i += 1024)
        *(float4*)&ps[i] = *(const float4*)(g_pool + (size_t)r0 * 1024 + i);
    __syncthreads();

    float acc[8];
    float bias = sb[tid];
    #pragma unroll
    for (int r = 0; r < 8; r++) acc[r] = bias;
    for (int i = 0; i < 1024; i++) {
        float w = sw[(size_t)i * 256 + tid];
        #pragma unroll
        for (int r = 0; r < 8; r++) acc[r] += ps[r * 1024 + i] * w;
    }
    #pragma unroll
    for (int r = 0; r < 8; r++)
        g_m[(size_t)(r0 + r) * 256 + tid] = acc[r];
}

// ---------------------------------------------------------------------------
// Classic 128x128x8 SGEMM, 256 threads, 8x8 micro-tile.
// C[M,N] = A[M,K] @ W[K,N] + bias, epilogue: 0=none, 1=exact GELU, 2=*mul
// M given by gridDim.y*128, N by gridDim.x*128. A assumed lda=K, C ldc given.
// ---------------------------------------------------------------------------
template <int EPI>
__global__ void __launch_bounds__(256) sgemm(
    const float* __restrict__ A, const float* __restrict__ W,
    const float* __restrict__ bias, const float* __restrict__ mul,
    float* __restrict__ C, int N, int K, int ldc, int ldm)
{
    __shared__ float As[8][128];
    __shared__ float Bs[8][128];
    int tid   = threadIdx.x;
    int mbase = blockIdx.y * 128;
    int nbase = blockIdx.x * 128;
    int ar = tid >> 1, ac = (tid & 1) * 4;
    int wr = tid >> 5, wc = (tid & 31) * 4;
    int ty = tid >> 4, tx = tid & 15;

    float acc[8][8] = {};

    for (int kt = 0; kt < K; kt += 8) {
        float4 av = *(const float4*)(A + (size_t)(mbase + ar) * K + kt + ac);
        As[ac + 0][ar] = av.x; As[ac + 1][ar] = av.y;
        As[ac + 2][ar] = av.z; As[ac + 3][ar] = av.w;
        *(float4*)&Bs[wr][wc] = *(const float4*)(W + (size_t)(kt + wr) * N + nbase + wc);
        __syncthreads();
        #pragma unroll
        for (int k = 0; k < 8; k++) {
            float a[8], b[8];
            *(float4*)(a)     = *(float4*)&As[k][ty * 8];
            *(float4*)(a + 4) = *(float4*)&As[k][ty * 8 + 4];
            *(float4*)(b)     = *(float4*)&Bs[k][tx * 8];
            *(float4*)(b + 4) = *(float4*)&Bs[k][tx * 8 + 4];
            #pragma unroll
            for (int i = 0; i < 8; i++)
                #pragma unroll
                for (int j = 0; j < 8; j++)
                    acc[i][j] += a[i] * b[j];
        }
        __syncthreads();
    }

    #pragma unroll
    for (int i = 0; i < 8; i++) {
        int gm = mbase + ty * 8 + i;
        #pragma unroll
        for (int j = 0; j < 8; j++) {
            int gn = nbase + tx * 8 + j;
            float v = acc[i][j] + bias[gn];
            if (EPI == 1) v = 0.5f * v * (1.0f + erff(v * 0.70710678118654752f));
            if (EPI == 2) v *= mul[(size_t)gm * ldm + gn];
            C[(size_t)gm * ldc + gn] = v;
        }
    }
}

// ---------------------------------------------------------------------------
// scores[b,nh,q,hw] = (m*d^-0.5) . k   block=(hw-chunk of 224, b*nh)
// ---------------------------------------------------------------------------
__global__ void scores_kernel()
{
    __shared__ float ms[49 * 32];
    int bn  = blockIdx.y;                  // b*8+nh
    int b   = bn >> 3, nh = bn & 7;
    int tid = threadIdx.x;                 // 224
    for (int i = tid; i < 49 * 32; i += 224)
        ms[i] = g_m[(size_t)(b * 49 + i / 32) * 256 + nh * 32 + (i & 31)]
                * 0.17677669529663689f;    // 1/sqrt(32)
    __syncthreads();

    int hw = blockIdx.x * 224 + tid;
    const float* kp = g_kv + (size_t)(b * HW + hw) * Cc + nh * 32;
    float kr[32];
    #pragma unroll
    for (int i = 0; i < 8; i++)
        *(float4*)(kr + i * 4) = *(const float4*)(kp + i * 4);

    float* out = g_sc + (size_t)bn * 49 * HW + hw;
    for (int q = 0; q < 49; q++) {
        float s = 0.f;
        #pragma unroll
        for (int dd = 0; dd < 32; dd++) s += ms[q * 32 + dd] * kr[dd];
        out[(size_t)q * HW] = s;
    }
}

// ---------------------------------------------------------------------------
// Softmax over hw (3136) — one block per (b,nh,q) row
// ---------------------------------------------------------------------------
__global__ void softmax_kernel()
{
    int row = blockIdx.x;
    float* p = g_sc + (size_t)row * HW;
    int tid = threadIdx.x;                 // 256
    __shared__ float red[256];

    float m = -1e30f;
    for (int i = tid; i < HW; i += 256) m = fmaxf(m, p[i]);
    red[tid] = m; __syncthreads();
    for (int s = 128; s > 0; s >>= 1) {
        if (tid < s) red[tid] = fmaxf(red[tid], red[tid + s]);
        __syncthreads();
    }
    float mx = red[0]; __syncthreads();

    float sum = 0.f;
    for (int i = tid; i < HW; i += 256) {
        float e = expf(p[i] - mx);
        p[i] = e;
        sum += e;
    }
    red[tid] = sum; __syncthreads();
    for (int s = 128; s > 0; s >>= 1) {
        if (tid < s) red[tid] += red[tid + s];
        __syncthreads();
    }
    float inv = 1.0f / red[0];
    for (int i = tid; i < HW; i += 256) p[i] *= inv;
}

// ---------------------------------------------------------------------------
// attn49 = probs @ v.  block=(b*nh, q-chunk of 7); 224 thr = 7q x 32d
// ---------------------------------------------------------------------------
__global__ void pv_kernel()
{
    int bn  = blockIdx.x;
    int b   = bn >> 3, nh = bn & 7;
    int tid = threadIdx.x;                 // 224
    int q   = blockIdx.y * 7 + (tid >> 5);
    int dd  = tid & 31;

    const float* pr = g_sc + ((size_t)bn * 49 + q) * HW;
    const float* vp = g_kv + C2 + nh * 32 + dd;
    int base = b * HW;

    float a0 = 0.f, a1 = 0.f, a2 = 0.f, a3 = 0.f;
    for (int hw = 0; hw < HW; hw += 4) {
        a0 += pr[hw]     * vp[(size_t)(base + hw)     * Cc];
        a1 += pr[hw + 1] * vp[(size_t)(base + hw + 1) * Cc];
        a2 += pr[hw + 2] * vp[(size_t)(base + hw + 2) * Cc];
        a3 += pr[hw + 3] * vp[(size_t)(base + hw + 3) * Cc];
    }
    g_a49[((size_t)bn * 49 + q) * 32 + dd] = a0 + a1 + a2 + a3;
}

// ---------------------------------------------------------------------------
// Bilinear 7->56 upsample (half-pixel, clamp) -> left half of xcat
// ---------------------------------------------------------------------------
__global__ void upsample_kernel()
{
    int p = blockIdx.x;                    // 0..BHW-1
    int b = p / HW;
    int rem = p % HW;
    int y = rem / Ww, x = rem % Ww;
    int c = threadIdx.x;                   // 256
    int nh = c >> 5, dd = c & 31;

    float sy = (y + 0.5f) * 0.125f - 0.5f;
    float sx = (x + 0.5f) * 0.125f - 0.5f;
    float fy = floorf(sy), fx = floorf(sx);
    float wy = sy - fy,    wx = sx - fx;
    int y0 = max(0, min(6, (int)fy)),     y1 = max(0, min(6, (int)fy + 1));
    int x0 = max(0, min(6, (int)fx)),     x1 = max(0, min(6, (int)fx + 1));

    const float* A = g_a49 + (size_t)(b * NHh + nh) * 49 * 32 + dd;
    float s00 = A[(y0 * 7 + x0) * 32];
    float s01 = A[(y0 * 7 + x1) * 32];
    float s10 = A[(y1 * 7 + x0) * 32];
    float s11 = A[(y1 * 7 + x1) * 32];
    float v = (1.f - wy) * ((1.f - wx) * s00 + wx * s01)
            +        wy  * ((1.f - wx) * s10 + wx * s11);
    g_xcat[(size_t)p * Cc + c] = v;
}

// ---------------------------------------------------------------------------
// Depthwise 7x7 conv, pad 3, channels-last (coalesced per tap)
// ---------------------------------------------------------------------------
__global__ void dwconv_kernel(const float* __restrict__ wgt, const float* __restrict__ cb)
{
    int p = blockIdx.x;
    int b = p / HW;
    int rem = p % HW;
    int y = rem / Ww, x = rem % Ww;
    int c = threadIdx.x;                   // 256

    float acc = cb[c];
    const float* wc_ = wgt + c * 49;
    #pragma unroll
    for (int ky = 0; ky < 7; ky++) {
        int iy = y + ky - 3;
        if (iy < 0 || iy >= Hh) continue;
        #pragma unroll
        for (int kx = 0; kx < 7; kx++) {
            int ix = x + kx - 3;
            if (ix < 0 || ix >= Ww) continue;
            acc += g_e1[((size_t)(b * HW) + iy * Ww + ix) * C2 + c] * wc_[ky * 7 + kx];
        }
    }
    g_e2[(size_t)p * C2 + c] = acc;
}

// ---------------------------------------------------------------------------
// Launch
// ---------------------------------------------------------------------------
extern "C" void kernel_launch(void* const* d_in, const int* in_sizes, int n_in,
                              void* d_out, int out_size)
{
    const float* x       = (const float*)d_in[0];
    const float* x_e     = (const float*)d_in[1];
    const float* norm_w  = (const float*)d_in[2];
    const float* norm_b  = (const float*)d_in[3];
    const float* norme_w = (const float*)d_in[4];
    const float* norme_b = (const float*)d_in[5];
    const float* qcut_w  = (const float*)d_in[6];
    const float* qcut_b  = (const float*)d_in[7];
    const float* l_w     = (const float*)d_in[8];
    const float* l_b     = (const float*)d_in[9];
    const float* kv_w    = (const float*)d_in[10];
    const float* kv_b    = (const float*)d_in[11];
    const float* sc_w    = (const float*)d_in[12];
    const float* sc_b    = (const float*)d_in[13];
    const float* efore_w = (const float*)d_in[14];
    const float* efore_b = (const float*)d_in[15];
    const float* econv_w = (const float*)d_in[16];
    const float* econv_b = (const float*)d_in[17];
    const float* eback_w = (const float*)d_in[18];
    const float* eback_b = (const float*)d_in[19];
    const float* proj_w  = (const float*)d_in[20];
    const float* proj_b  = (const float*)d_in[21];
    const float* proje_w = (const float*)d_in[22];
    const float* proje_b = (const float*)d_in[23];
    float* out = (float*)d_out;

    float *xn, *xen, *bfeat, *kv, *xcat, *cut, *e1, *e2;
    cudaGetSymbolAddress((void**)&xn,    g_xn);
    cudaGetSymbolAddress((void**)&xen,   g_xen);
    cudaGetSymbolAddress((void**)&bfeat, g_bfeat);
    cudaGetSymbolAddress((void**)&kv,    g_kv);
    cudaGetSymbolAddress((void**)&xcat,  g_xcat);
    cudaGetSymbolAddress((void**)&cut,   g_cut);
    cudaGetSymbolAddress((void**)&e1,    g_e1);
    cudaGetSymbolAddress((void**)&e2,    g_e2);

    // 1. LayerNorms (both tensors in one grid)
    ln_kernel<<<2 * BHW, 128>>>(x, x_e, norm_w, norm_b, norme_w, norme_b);

    // 2-3. pooled queries
    pool_kernel<<<Bn * 49, 256>>>();
    mproj_kernel<<<49, 256>>>(sc_w, sc_b);

    // 4. cutted = xn @ qcut_w            [25088,512]x[512,256]
    sgemm<0><<<dim3(2, 196), 256>>>(xn, qcut_w, qcut_b, nullptr, cut, 256, 512, 256, 0);
    // 5. bfeat = gelu(xn @ l_w)          [25088,512]x[512,512]
    sgemm<1><<<dim3(4, 196), 256>>>(xn, l_w, l_b, nullptr, bfeat, 512, 512, 512, 0);
    // 6. kv = bfeat @ kv_w               [25088,512]x[512,512]
    sgemm<0><<<dim3(4, 196), 256>>>(bfeat, kv_w, kv_b, nullptr, kv, 512, 512, 512, 0);

    // 7-9. attention
    scores_kernel<<<dim3(14, 64), 224>>>();
    softmax_kernel<<<Bn * NHh * 49, 256>>>();
    pv_kernel<<<dim3(64, 7), 224>>>();

    // 10. upsample -> xcat[:, 0:256]
    upsample_kernel<<<BHW, 256>>>();

    // 11. e1 = xen @ efore_w             [25088,512]x[512,256]
    sgemm<0><<<dim3(2, 196), 256>>>(xen, efore_w, efore_b, nullptr, e1, 256, 512, 256, 0);
    // 12. depthwise conv
    dwconv_kernel<<<BHW, 256>>>(econv_w, econv_b);
    // 13. xcat[:, 256:512] = (e2 @ eback_w + b) * cutted   [25088,256]x[256,256]
    sgemm<2><<<dim3(2, 196), 256>>>(e2, eback_w, eback_b, cut, xcat + 256, 256, 256, 512, 256);

    // 14-15. output projections (x_out first, then x_e_out)
    sgemm<0><<<dim3(4, 196), 256>>>(xcat, proj_w, proj_b, nullptr, out, 512, 512, 512, 0);
    sgemm<0><<<dim3(4, 196), 256>>>(xcat, proje_w, proje_b, nullptr,
                                    out + (size_t)BHW * Cc, 512, 512, 512, 0);
}

// round 3
// speedup vs baseline: 1.9870x; 1.9870x over previous
#include <cuda_runtime.h>
#include <cstdint>
#include <math.h>

// Problem constants
#define Bn   8
#define Hh   56
#define Ww   56
#define Cc   512
#define C2   256
#define HW   3136
#define BHW  25088
#define NHh  8

// ===========================================================================
// Scratch
// ===========================================================================
__device__ float g_xn   [BHW * Cc];
__device__ float g_xen  [BHW * Cc];
__device__ float g_bfeat[BHW * Cc];
__device__ float g_kv   [BHW * Cc];
__device__ float g_xcat [BHW * Cc];
__device__ float g_cut  [BHW * C2];
__device__ float g_e1   [BHW * C2];
__device__ float g_e2   [BHW * C2];
__device__ float g_pool [Bn * 49 * 1024];
__device__ float g_m    [Bn * 49 * C2];
__device__ float g_sc   [Bn * NHh * 49 * HW];
__device__ float g_a49p [4 * Bn * NHh * 49 * 32];

// ===========================================================================
// tf32 helpers
// ===========================================================================
__device__ __forceinline__ uint32_t f2tf32(float x) {
    uint32_t y;
    asm("cvt.rna.tf32.f32 %0, %1;" : "=r"(y) : "f"(x));
    return y;
}

#define MMA_TF32(c, a0, a1, a2, a3, b0, b1) \
    asm volatile("mma.sync.aligned.m16n8k8.row.col.f32.tf32.tf32.f32 " \
        "{%0,%1,%2,%3}, {%4,%5,%6,%7}, {%8,%9}, {%0,%1,%2,%3};" \
        : "+f"((c)[0]), "+f"((c)[1]), "+f"((c)[2]), "+f"((c)[3]) \
        : "r"(a0), "r"(a1), "r"(a2), "r"(a3), "r"(b0), "r"(b1))

// ===========================================================================
// tf32 mma.sync GEMM:
//   C[M, N] = A[M,K] @ W[K,N] + bias,  EPI: 0=none, 1=exact GELU, 2=*mul
//   block tile 128x128xBK16, 8 warps (4 M x 2 N), warp tile 32x64
// ===========================================================================
template <int EPI>
__global__ void __launch_bounds__(256, 2) gemm_mma(
    const float* __restrict__ A, const float* __restrict__ W,
    const float* __restrict__ bias, const float* __restrict__ mul,
    float* __restrict__ C, int K, int N, int ldc, int ldm)
{
    __shared__ uint32_t As[2][16][132];
    __shared__ uint32_t Bs[2][16][132];
    __shared__ float sbias[128];

    const int tid  = threadIdx.x;
    const int warp = tid >> 5, lane = tid & 31;
    const int wm = warp & 3, wn = warp >> 2;         // 4 x 2 warps
    const int mbase = blockIdx.y * 128;
    const int nbase = blockIdx.x * 128;

    // global-load indexing
    const int ar = tid >> 1,        aco = (tid & 1) * 8;   // A: row, k-offset
    const int br = tid >> 4,        bco = (tid & 15) * 8;  // B: k-row, n-offset

    if (tid < 128) sbias[tid] = bias[nbase + tid];

    const int NK = K >> 4;
    float c[2][8][4];
    #pragma unroll
    for (int i = 0; i < 2; i++)
        #pragma unroll
        for (int j = 0; j < 8; j++)
            #pragma unroll
            for (int r = 0; r < 4; r++) c[i][j][r] = 0.f;

    const float* pa = A + (size_t)(mbase + ar) * K + aco;
    const float* pb = W + (size_t)br * N + nbase + bco;

    float4 ra0 = *(const float4*)(pa);
    float4 ra1 = *(const float4*)(pa + 4);
    float4 rb0 = *(const float4*)(pb);
    float4 rb1 = *(const float4*)(pb + 4);

    auto store_stage = [&](int s, const float4& a0v, const float4& a1v,
                           const float4& b0v, const float4& b1v) {
        As[s][aco + 0][ar] = f2tf32(a0v.x); As[s][aco + 1][ar] = f2tf32(a0v.y);
        As[s][aco + 2][ar] = f2tf32(a0v.z); As[s][aco + 3][ar] = f2tf32(a0v.w);
        As[s][aco + 4][ar] = f2tf32(a1v.x); As[s][aco + 5][ar] = f2tf32(a1v.y);
        As[s][aco + 6][ar] = f2tf32(a1v.z); As[s][aco + 7][ar] = f2tf32(a1v.w);
        uint4 t0 = make_uint4(f2tf32(b0v.x), f2tf32(b0v.y), f2tf32(b0v.z), f2tf32(b0v.w));
        uint4 t1 = make_uint4(f2tf32(b1v.x), f2tf32(b1v.y), f2tf32(b1v.z), f2tf32(b1v.w));
        *(uint4*)&Bs[s][br][bco]     = t0;
        *(uint4*)&Bs[s][br][bco + 4] = t1;
    };

    store_stage(0, ra0, ra1, rb0, rb1);
    __syncthreads();

    const int l4 = lane >> 2, lk = lane & 3;

    for (int kt = 0; kt < NK; kt++) {
        const int s = kt & 1;
        // prefetch next tile into registers
        if (kt + 1 < NK) {
            const float* na = pa + (kt + 1) * 16;
            const float* nb = pb + (size_t)(kt + 1) * 16 * N;
            ra0 = *(const float4*)(na);
            ra1 = *(const float4*)(na + 4);
            rb0 = *(const float4*)(nb);
            rb1 = *(const float4*)(nb + 4);
        }
        // compute on stage s
        #pragma unroll
        for (int ks = 0; ks < 2; ks++) {
            const int k0 = ks * 8;
            uint32_t af[2][4];
            #pragma unroll
            for (int i = 0; i < 2; i++) {
                int m0 = wm * 32 + i * 16;
                af[i][0] = As[s][k0 + lk][m0 + l4];
                af[i][1] = As[s][k0 + lk][m0 + 8 + l4];
                af[i][2] = As[s][k0 + lk + 4][m0 + l4];
                af[i][3] = As[s][k0 + lk + 4][m0 + 8 + l4];
            }
            uint32_t bf[8][2];
            #pragma unroll
            for (int j = 0; j < 8; j++) {
                int n0 = wn * 64 + j * 8 + l4;
                bf[j][0] = Bs[s][k0 + lk][n0];
                bf[j][1] = Bs[s][k0 + lk + 4][n0];
            }
            #pragma unroll
            for (int i = 0; i < 2; i++)
                #pragma unroll
                for (int j = 0; j < 8; j++)
                    MMA_TF32(c[i][j], af[i][0], af[i][1], af[i][2], af[i][3],
                             bf[j][0], bf[j][1]);
        }
        if (kt + 1 < NK) {
            __syncthreads();           // everyone done reading stage s^1 (2 iters ago)
            store_stage(s ^ 1, ra0, ra1, rb0, rb1);
            __syncthreads();
        }
    }

    // epilogue: direct stores (float2 pairs)
    #pragma unroll
    for (int i = 0; i < 2; i++) {
        int row0 = mbase + wm * 32 + i * 16 + l4;
        #pragma unroll
        for (int j = 0; j < 8; j++) {
            int colL = wn * 64 + j * 8 + lk * 2;
            int col = nbase + colL;
            float v0 = c[i][j][0] + sbias[colL];
            float v1 = c[i][j][1] + sbias[colL + 1];
            float v2 = c[i][j][2] + sbias[colL];
            float v3 = c[i][j][3] + sbias[colL + 1];
            if (EPI == 1) {
                v0 = 0.5f * v0 * (1.0f + erff(v0 * 0.70710678118654752f));
                v1 = 0.5f * v1 * (1.0f + erff(v1 * 0.70710678118654752f));
                v2 = 0.5f * v2 * (1.0f + erff(v2 * 0.70710678118654752f));
                v3 = 0.5f * v3 * (1.0f + erff(v3 * 0.70710678118654752f));
            }
            if (EPI == 2) {
                float2 m0 = *(const float2*)(mul + (size_t)row0 * ldm + col);
                float2 m1 = *(const float2*)(mul + (size_t)(row0 + 8) * ldm + col);
                v0 *= m0.x; v1 *= m0.y; v2 *= m1.x; v3 *= m1.y;
            }
            *(float2*)(C + (size_t)row0 * ldc + col)       = make_float2(v0, v1);
            *(float2*)(C + (size_t)(row0 + 8) * ldc + col) = make_float2(v2, v3);
        }
    }
}

// ===========================================================================
// LayerNorm
// ===========================================================================
__global__ void ln_kernel(const float* __restrict__ x, const float* __restrict__ xe,
                          const float* __restrict__ nw, const float* __restrict__ nb,
                          const float* __restrict__ ew, const float* __restrict__ eb)
{
    int p = blockIdx.x, tid = threadIdx.x;
    bool sec = p >= BHW;
    int pix = sec ? p - BHW : p;
    const float* src = (sec ? xe : x) + (size_t)pix * Cc;
    float*       dst = (sec ? g_xen : g_xn) + (size_t)pix * Cc;
    const float* w = sec ? ew : nw;
    const float* bb = sec ? eb : nb;

    float4 v = *(const float4*)(src + tid * 4);
    float s  = v.x + v.y + v.z + v.w;
    float ss = v.x*v.x + v.y*v.y + v.z*v.z + v.w*v.w;
    #pragma unroll
    for (int o = 16; o > 0; o >>= 1) {
        s  += __shfl_xor_sync(0xffffffffu, s,  o);
        ss += __shfl_xor_sync(0xffffffffu, ss, o);
    }
    __shared__ float sm[4], sm2[4];
    int wid = tid >> 5;
    if ((tid & 31) == 0) { sm[wid] = s; sm2[wid] = ss; }
    __syncthreads();
    s = sm[0] + sm[1] + sm[2] + sm[3];
    ss = sm2[0] + sm2[1] + sm2[2] + sm2[3];
    float mu = s * (1.0f / Cc);
    float var = ss * (1.0f / Cc) - mu * mu;
    float inv = rsqrtf(var + 1e-6f);
    float4 wv = *(const float4*)(w + tid * 4);
    float4 bv = *(const float4*)(bb + tid * 4);
    float4 o;
    o.x = (v.x - mu) * inv * wv.x + bv.x;
    o.y = (v.y - mu) * inv * wv.y + bv.y;
    o.z = (v.z - mu) * inv * wv.z + bv.z;
    o.w = (v.w - mu) * inv * wv.w + bv.w;
    *(float4*)(dst + tid * 4) = o;
}

// ===========================================================================
// Pool + mproj
// ===========================================================================
__global__ void pool_kernel()
{
    int blk = blockIdx.x;
    int b = blk / 49, pp = blk % 49;
    int pi = pp / 7, pj = pp % 7;
    int c4 = threadIdx.x * 4;
    const float* src = (c4 < Cc) ? g_xn : g_xen;
    int cc = (c4 < Cc) ? c4 : c4 - Cc;
    float4 s = make_float4(0.f, 0.f, 0.f, 0.f);
    for (int ii = 0; ii < 8; ii++)
        for (int jj = 0; jj < 8; jj++) {
            int pix = b * HW + (pi * 8 + ii) * Ww + (pj * 8 + jj);
            float4 v = *(const float4*)(src + (size_t)pix * Cc + cc);
            s.x += v.x; s.y += v.y; s.z += v.z; s.w += v.w;
        }
    const float inv = 1.0f / 64.0f;
    *(float4*)(g_pool + (size_t)blk * 1024 + c4) =
        make_float4(s.x * inv, s.y * inv, s.z * inv, s.w * inv);
}

__global__ void mproj_kernel(const float* __restrict__ sw, const float* __restrict__ sb)
{
    __shared__ float ps[8 * 1024];
    int r0 = blockIdx.x * 8, tid = threadIdx.x;
    for (int i = tid * 4; i < 8 * 1024; i += 1024)
        *(float4*)&ps[i] = *(const float4*)(g_pool + (size_t)r0 * 1024 + i);
    __syncthreads();
    float acc[8];
    float bias = sb[tid];
    #pragma unroll
    for (int r = 0; r < 8; r++) acc[r] = bias;
    for (int i = 0; i < 1024; i++) {
        float w = sw[(size_t)i * 256 + tid];
        #pragma unroll
        for (int r = 0; r < 8; r++) acc[r] += ps[r * 1024 + i] * w;
    }
    #pragma unroll
    for (int r = 0; r < 8; r++)
        g_m[(size_t)(r0 + r) * 256 + tid] = acc[r];
}

// ===========================================================================
// scores
// ===========================================================================
__global__ void scores_kernel()
{
    __shared__ float ms[49 * 32];
    int bn = blockIdx.y;
    int b = bn >> 3, nh = bn & 7;
    int tid = threadIdx.x;
    for (int i = tid; i < 49 * 32; i += 224)
        ms[i] = g_m[(size_t)(b * 49 + i / 32) * 256 + nh * 32 + (i & 31)]
                * 0.17677669529663689f;
    __syncthreads();
    int hw = blockIdx.x * 224 + tid;
    const float* kp = g_kv + (size_t)(b * HW + hw) * Cc + nh * 32;
    float kr[32];
    #pragma unroll
    for (int i = 0; i < 8; i++)
        *(float4*)(kr + i * 4) = *(const float4*)(kp + i * 4);
    float* out = g_sc + (size_t)bn * 49 * HW + hw;
    for (int q = 0; q < 49; q++) {
        float s = 0.f;
        #pragma unroll
        for (int dd = 0; dd < 32; dd++) s += ms[q * 32 + dd] * kr[dd];
        out[(size_t)q * HW] = s;
    }
}

// ===========================================================================
// Softmax: single gmem read + write via smem buffer
// ===========================================================================
__global__ void softmax2()
{
    __shared__ float buf[HW];
    __shared__ float red[256];
    int row = blockIdx.x, tid = threadIdx.x;
    float* p = g_sc + (size_t)row * HW;
    float m = -1e30f;
    for (int i = tid; i < HW; i += 256) { float v = p[i]; buf[i] = v; m = fmaxf(m, v); }
    red[tid] = m; __syncthreads();
    for (int s = 128; s > 0; s >>= 1) {
        if (tid < s) red[tid] = fmaxf(red[tid], red[tid + s]);
        __syncthreads();
    }
    float mx = red[0]; __syncthreads();
    float sum = 0.f;
    for (int i = tid; i < HW; i += 256) { float e = __expf(buf[i] - mx); buf[i] = e; sum += e; }
    red[tid] = sum; __syncthreads();
    for (int s = 128; s > 0; s >>= 1) {
        if (tid < s) red[tid] += red[tid + s];
        __syncthreads();
    }
    float inv = 1.0f / red[0];
    for (int i = tid; i < HW; i += 256) p[i] = buf[i] * inv;
}

// ===========================================================================
// pv: smem-tiled probs @ v, 4-way HW split -> partials
// ===========================================================================
__global__ void pv2()
{
    __shared__ float vs[112][32];
    int bn = blockIdx.x, cp = blockIdx.y;
    int b = bn >> 3, nh = bn & 7;
    int tid = threadIdx.x;
    int d = tid & 31, qg = tid >> 5;
    float acc[7] = {0.f, 0.f, 0.f, 0.f, 0.f, 0.f, 0.f};
    int hw0 = cp * 784;

    for (int ch = 0; ch < 784; ch += 112) {
        __syncthreads();
        for (int u = tid; u < 112 * 8; u += 256) {
            int r = u >> 3, c = u & 7;
            *(float4*)&vs[r][c * 4] = *(const float4*)(
                g_kv + (size_t)(b * HW + hw0 + ch + r) * Cc + C2 + nh * 32 + c * 4);
        }
        __syncthreads();
        if (qg < 7) {
            #pragma unroll
            for (int j = 0; j < 7; j++) {
                int q = qg * 7 + j;
                const float* pr = g_sc + ((size_t)bn * 49 + q) * HW + hw0 + ch;
                float a = acc[j];
                for (int i = 0; i < 112; i++) a += pr[i] * vs[i][d];
                acc[j] = a;
            }
        }
    }
    if (qg < 7) {
        #pragma unroll
        for (int j = 0; j < 7; j++)
            g_a49p[((size_t)cp * 64 * 49 + (size_t)bn * 49 + qg * 7 + j) * 32 + d] = acc[j];
    }
}

// ===========================================================================
// Bilinear 7->56 upsample with 4-partial reduction -> xcat[:, 0:256]
// ===========================================================================
__global__ void upsample_kernel()
{
    int p = blockIdx.x;
    int b = p / HW, rem = p % HW;
    int y = rem / Ww, x = rem % Ww;
    int c = threadIdx.x;
    int nh = c >> 5, dd = c & 31;
    int bn = b * NHh + nh;

    float sy = (y + 0.5f) * 0.125f - 0.5f;
    float sx = (x + 0.5f) * 0.125f - 0.5f;
    float fy = floorf(sy), fx = floorf(sx);
    float wy = sy - fy, wx = sx - fx;
    int y0 = max(0, min(6, (int)fy)), y1 = max(0, min(6, (int)fy + 1));
    int x0 = max(0, min(6, (int)fx)), x1 = max(0, min(6, (int)fx + 1));

    const size_t P = (size_t)64 * 49 * 32;
    size_t base = ((size_t)bn * 49) * 32 + dd;
    #define APART(q) (g_a49p[base + (size_t)(q) * 32] + g_a49p[P + base + (size_t)(q) * 32] \
                    + g_a49p[2 * P + base + (size_t)(q) * 32] + g_a49p[3 * P + base + (size_t)(q) * 32])
    float s00 = APART(y0 * 7 + x0);
    float s01 = APART(y0 * 7 + x1);
    float s10 = APART(y1 * 7 + x0);
    float s11 = APART(y1 * 7 + x1);
    #undef APART
    float v = (1.f - wy) * ((1.f - wx) * s00 + wx * s01)
            +        wy  * ((1.f - wx) * s10 + wx * s11);
    g_xcat[(size_t)p * Cc + c] = v;
}

// ===========================================================================
// Depthwise 7x7 conv, smem-tiled: 8x8 spatial x 32 channels per block
// ===========================================================================
__global__ void dwconv2(const float* __restrict__ wgt, const float* __restrict__ cb)
{
    __shared__ float tile[196 * 32];       // 14x14 halo x 32 ch
    int sbk = blockIdx.x;
    int b = sbk / 49, t49 = sbk % 49;
    int ty0 = (t49 / 7) * 8, tx0 = (t49 % 7) * 8;
    int cg = blockIdx.y;
    int tid = threadIdx.x;
    int cl = tid & 31, pxg = tid >> 5;
    int ch = cg * 32 + cl;

    for (int u = tid; u < 196 * 8; u += 256) {
        int px = u >> 3, c4 = u & 7;
        int iy = ty0 + px / 14 - 3;
        int ix = tx0 + px % 14 - 3;
        float4 v = make_float4(0.f, 0.f, 0.f, 0.f);
        if (iy >= 0 && iy < Hh && ix >= 0 && ix < Ww)
            v = *(const float4*)(g_e1 + ((size_t)(b * HW) + iy * Ww + ix) * C2 + cg * 32 + c4 * 4);
        *(float4*)&tile[px * 32 + c4 * 4] = v;
    }
    __syncthreads();

    float wr[49];
    #pragma unroll
    for (int i = 0; i < 49; i++) wr[i] = wgt[ch * 49 + i];
    float bias = cb[ch];

    #pragma unroll
    for (int k = 0; k < 8; k++) {
        int o = pxg * 8 + k;
        int oy = o >> 3, ox = o & 7;
        float acc = bias;
        #pragma unroll
        for (int ky = 0; ky < 7; ky++)
            #pragma unroll
            for (int kx = 0; kx < 7; kx++)
                acc += tile[((oy + ky) * 14 + ox + kx) * 32 + cl] * wr[ky * 7 + kx];
        g_e2[((size_t)(b * HW) + (ty0 + oy) * Ww + tx0 + ox) * C2 + ch] = acc;
    }
}

// ===========================================================================
// Launch
// ===========================================================================
extern "C" void kernel_launch(void* const* d_in, const int* in_sizes, int n_in,
                              void* d_out, int out_size)
{
    const float* x       = (const float*)d_in[0];
    const float* x_e     = (const float*)d_in[1];
    const float* norm_w  = (const float*)d_in[2];
    const float* norm_b  = (const float*)d_in[3];
    const float* norme_w = (const float*)d_in[4];
    const float* norme_b = (const float*)d_in[5];
    const float* qcut_w  = (const float*)d_in[6];
    const float* qcut_b  = (const float*)d_in[7];
    const float* l_w     = (const float*)d_in[8];
    const float* l_b     = (const float*)d_in[9];
    const float* kv_w    = (const float*)d_in[10];
    const float* kv_b    = (const float*)d_in[11];
    const float* sc_w    = (const float*)d_in[12];
    const float* sc_b    = (const float*)d_in[13];
    const float* efore_w = (const float*)d_in[14];
    const float* efore_b = (const float*)d_in[15];
    const float* econv_w = (const float*)d_in[16];
    const float* econv_b = (const float*)d_in[17];
    const float* eback_w = (const float*)d_in[18];
    const float* eback_b = (const float*)d_in[19];
    const float* proj_w  = (const float*)d_in[20];
    const float* proj_b  = (const float*)d_in[21];
    const float* proje_w = (const float*)d_in[22];
    const float* proje_b = (const float*)d_in[23];
    float* out = (float*)d_out;

    float *xn, *xen, *bfeat, *kv, *xcat, *cut, *e1, *e2;
    cudaGetSymbolAddress((void**)&xn,    g_xn);
    cudaGetSymbolAddress((void**)&xen,   g_xen);
    cudaGetSymbolAddress((void**)&bfeat, g_bfeat);
    cudaGetSymbolAddress((void**)&kv,    g_kv);
    cudaGetSymbolAddress((void**)&xcat,  g_xcat);
    cudaGetSymbolAddress((void**)&cut,   g_cut);
    cudaGetSymbolAddress((void**)&e1,    g_e1);
    cudaGetSymbolAddress((void**)&e2,    g_e2);

    // 1. LayerNorms
    ln_kernel<<<2 * BHW, 128>>>(x, x_e, norm_w, norm_b, norme_w, norme_b);

    // 2-3. pooled queries
    pool_kernel<<<Bn * 49, 256>>>();
    mproj_kernel<<<49, 256>>>(sc_w, sc_b);

    // 4. cutted = xn @ qcut_w
    gemm_mma<0><<<dim3(2, 196), 256>>>(xn, qcut_w, qcut_b, nullptr, cut, 512, 256, 256, 0);
    // 5. bfeat = gelu(xn @ l_w)
    gemm_mma<1><<<dim3(4, 196), 256>>>(xn, l_w, l_b, nullptr, bfeat, 512, 512, 512, 0);
    // 6. kv = bfeat @ kv_w
    gemm_mma<0><<<dim3(4, 196), 256>>>(bfeat, kv_w, kv_b, nullptr, kv, 512, 512, 512, 0);

    // 7-9. attention
    scores_kernel<<<dim3(14, 64), 224>>>();
    softmax2<<<Bn * NHh * 49, 256>>>();
    pv2<<<dim3(64, 4), 256>>>();

    // 10. upsample -> xcat[:, 0:256]
    upsample_kernel<<<BHW, 256>>>();

    // 11-13. gating branch
    gemm_mma<0><<<dim3(2, 196), 256>>>(xen, efore_w, efore_b, nullptr, e1, 512, 256, 256, 0);
    dwconv2<<<dim3(392, 8), 256>>>(econv_w, econv_b);
    gemm_mma<2><<<dim3(2, 196), 256>>>(e2, eback_w, eback_b, cut, xcat + 256, 256, 256, 512, 256);

    // 14-15. output projections
    gemm_mma<0><<<dim3(4, 196), 256>>>(xcat, proj_w, proj_b, nullptr, out, 512, 512, 512, 0);
    gemm_mma<0><<<dim3(4, 196), 256>>>(xcat, proje_w, proje_b, nullptr,
                                       out + (size_t)BHW * Cc, 512, 512, 512, 0);
}

// round 4
// speedup vs baseline: 2.7361x; 1.3770x over previous
#include <cuda_runtime.h>
#include <cstdint>
#include <math.h>

// Problem constants
#define Bn   8
#define Hh   56
#define Ww   56
#define Cc   512
#define C2   256
#define HW   3136
#define BHW  25088
#define NHh  8

// ===========================================================================
// Scratch
// ===========================================================================
__device__ float g_xn   [BHW * Cc];
__device__ float g_xen  [BHW * Cc];
__device__ float g_bfeat[BHW * Cc];
__device__ float g_kv   [BHW * Cc];
__device__ float g_xcat [BHW * Cc];
__device__ float g_cut  [BHW * C2];
__device__ float g_e1   [BHW * C2];
__device__ float g_e2   [BHW * C2];
__device__ float g_pool [Bn * 49 * 1024];
__device__ float g_m    [Bn * 49 * C2];
__device__ float g_a49p [4 * 64 * 49 * 32];
__device__ float g_mpart[4 * 64 * 49];
__device__ float g_spart[4 * 64 * 49];
__device__ float g_a49  [64 * 49 * 32];
__device__ float g_wt   [1376256];         // tf32-rounded weights

#define WT_QCUT  0
#define WT_L     131072
#define WT_KV    393216
#define WT_EFORE 655360
#define WT_EBACK 786432
#define WT_PROJ  851968
#define WT_PROJE 1114112

// ===========================================================================
// helpers
// ===========================================================================
__device__ __forceinline__ uint32_t f2tf32(float x) {
    uint32_t y;
    asm("cvt.rna.tf32.f32 %0, %1;" : "=r"(y) : "f"(x));
    return y;
}
__device__ __forceinline__ float rnd32(float x) { return __uint_as_float(f2tf32(x)); }

__device__ __forceinline__ void cpasync16(void* dst, const void* src) {
    uint32_t d = (uint32_t)__cvta_generic_to_shared(dst);
    asm volatile("cp.async.cg.shared.global [%0], [%1], 16;" :: "r"(d), "l"(src));
}
#define CP_COMMIT() asm volatile("cp.async.commit_group;" ::: "memory")
#define CP_WAIT2()  asm volatile("cp.async.wait_group 2;" ::: "memory")

#define MMA_TF32(c, a0, a1, a2, a3, b0, b1) \
    asm volatile("mma.sync.aligned.m16n8k8.row.col.f32.tf32.tf32.f32 " \
        "{%0,%1,%2,%3}, {%4,%5,%6,%7}, {%8,%9}, {%0,%1,%2,%3};" \
        : "+f"((c)[0]), "+f"((c)[1]), "+f"((c)[2]), "+f"((c)[3]) \
        : "r"(a0), "r"(a1), "r"(a2), "r"(a3), "r"(b0), "r"(b1))

// ===========================================================================
// round weights to tf32 bit patterns
// ===========================================================================
__global__ void round_tf32_k(const float* __restrict__ src, float* __restrict__ dst, int n)
{
    int i = blockIdx.x * 256 + threadIdx.x;
    if (i < n) dst[i] = rnd32(src[i]);
}

// ===========================================================================
// tf32 mma.sync GEMM, 4-stage cp.async pipeline.
//   C[M,N] = A[M,K] @ W[K,N] + bias.  A and W must be tf32-pre-rounded.
//   EPI: 0=none 1=exact GELU 2=*mul ; RND: round output to tf32
//   128x128 block tile, 8 warps (4M x 2N), warp tile 32x64.
// smem: As 4 stages [128][20], Bs 4 stages [16][136], bias 128
// ===========================================================================
#define AS_STRIDE 20
#define BS_STRIDE 136
#define AS_STAGE  (128 * AS_STRIDE)
#define BS_STAGE  (16 * BS_STRIDE)
#define SMEM_GEMM ((4 * AS_STAGE + 4 * BS_STAGE + 128) * 4)

template <int EPI, int RND>
__global__ void __launch_bounds__(256, 2) gemm_mma(
    const float* __restrict__ A, const float* __restrict__ W,
    const float* __restrict__ bias, const float* __restrict__ mul,
    float* __restrict__ C, int K, int N, int ldc, int ldm)
{
    extern __shared__ float smp[];
    float* As = smp;
    float* Bs = smp + 4 * AS_STAGE;
    float* sbias = Bs + 4 * BS_STAGE;

    const int tid = threadIdx.x;
    const int warp = tid >> 5, lane = tid & 31;
    const int wm = warp & 3, wn = warp >> 2;
    const int mbase = blockIdx.y * 128;
    const int nbase = blockIdx.x * 128;
    const int l4 = lane >> 2, lk = lane & 3;

    const int arow = tid >> 1, ac4 = (tid & 1) * 2;   // A: one row, two 16B chunks
    const int brow = tid >> 4, bc0 = (tid & 15) * 2;  // B: one k-row, two 16B chunks

    if (tid < 128) sbias[tid] = bias[nbase + tid];

    const int NK = K >> 4;

    auto issue_stage = [&](int kt, int s) {
        float* a_s = As + s * AS_STAGE;
        float* b_s = Bs + s * BS_STAGE;
        const float* ga = A + (size_t)(mbase + arow) * K + kt * 16;
        cpasync16(a_s + arow * AS_STRIDE + ac4 * 4,       ga + ac4 * 4);
        cpasync16(a_s + arow * AS_STRIDE + (ac4 + 1) * 4, ga + (ac4 + 1) * 4);
        const float* gb = W + (size_t)(kt * 16 + brow) * N + nbase;
        cpasync16(b_s + brow * BS_STRIDE + bc0 * 4,       gb + bc0 * 4);
        cpasync16(b_s + brow * BS_STRIDE + (bc0 + 1) * 4, gb + (bc0 + 1) * 4);
        CP_COMMIT();
    };

    float c[2][8][4];
    #pragma unroll
    for (int i = 0; i < 2; i++)
        #pragma unroll
        for (int j = 0; j < 8; j++)
            #pragma unroll
            for (int r = 0; r < 4; r++) c[i][j][r] = 0.f;

    issue_stage(0, 0); issue_stage(1, 1); issue_stage(2, 2);

    for (int kt = 0; kt < NK; kt++) {
        const int s = kt & 3;
        CP_WAIT2();
        __syncthreads();
        if (kt + 3 < NK) issue_stage(kt + 3, (kt + 3) & 3);

        const float* a_s = As + s * AS_STAGE;
        const float* b_s = Bs + s * BS_STAGE;
        #pragma unroll
        for (int ks = 0; ks < 2; ks++) {
            const int k0 = ks * 8;
            uint32_t af[2][4];
            #pragma unroll
            for (int i = 0; i < 2; i++) {
                int m0 = wm * 32 + i * 16;
                af[i][0] = __float_as_uint(a_s[(m0 + l4) * AS_STRIDE + k0 + lk]);
                af[i][1] = __float_as_uint(a_s[(m0 + 8 + l4) * AS_STRIDE + k0 + lk]);
                af[i][2] = __float_as_uint(a_s[(m0 + l4) * AS_STRIDE + k0 + lk + 4]);
                af[i][3] = __float_as_uint(a_s[(m0 + 8 + l4) * AS_STRIDE + k0 + lk + 4]);
            }
            uint32_t bf[8][2];
            #pragma unroll
            for (int j = 0; j < 8; j++) {
                int n0 = wn * 64 + j * 8 + l4;
                bf[j][0] = __float_as_uint(b_s[(k0 + lk) * BS_STRIDE + n0]);
                bf[j][1] = __float_as_uint(b_s[(k0 + lk + 4) * BS_STRIDE + n0]);
            }
            #pragma unroll
            for (int i = 0; i < 2; i++)
                #pragma unroll
                for (int j = 0; j < 8; j++)
                    MMA_TF32(c[i][j], af[i][0], af[i][1], af[i][2], af[i][3],
                             bf[j][0], bf[j][1]);
        }
    }

    // epilogue
    #pragma unroll
    for (int i = 0; i < 2; i++) {
        int row0 = mbase + wm * 32 + i * 16 + l4;
        #pragma unroll
        for (int j = 0; j < 8; j++) {
            int colL = wn * 64 + j * 8 + lk * 2;
            int col = nbase + colL;
            float v0 = c[i][j][0] + sbias[colL];
            float v1 = c[i][j][1] + sbias[colL + 1];
            float v2 = c[i][j][2] + sbias[colL];
            float v3 = c[i][j][3] + sbias[colL + 1];
            if (EPI == 1) {
                v0 = 0.5f * v0 * (1.0f + erff(v0 * 0.70710678118654752f));
                v1 = 0.5f * v1 * (1.0f + erff(v1 * 0.70710678118654752f));
                v2 = 0.5f * v2 * (1.0f + erff(v2 * 0.70710678118654752f));
                v3 = 0.5f * v3 * (1.0f + erff(v3 * 0.70710678118654752f));
            }
            if (EPI == 2) {
                float2 m0 = *(const float2*)(mul + (size_t)row0 * ldm + col);
                float2 m1 = *(const float2*)(mul + (size_t)(row0 + 8) * ldm + col);
                v0 *= m0.x; v1 *= m0.y; v2 *= m1.x; v3 *= m1.y;
            }
            if (RND) { v0 = rnd32(v0); v1 = rnd32(v1); v2 = rnd32(v2); v3 = rnd32(v3); }
            *(float2*)(C + (size_t)row0 * ldc + col)       = make_float2(v0, v1);
            *(float2*)(C + (size_t)(row0 + 8) * ldc + col) = make_float2(v2, v3);
        }
    }
}

// ===========================================================================
// LayerNorm (tf32-rounded output)
// ===========================================================================
__global__ void ln_kernel(const float* __restrict__ x, const float* __restrict__ xe,
                          const float* __restrict__ nw, const float* __restrict__ nb,
                          const float* __restrict__ ew, const float* __restrict__ eb)
{
    int p = blockIdx.x, tid = threadIdx.x;
    bool sec = p >= BHW;
    int pix = sec ? p - BHW : p;
    const float* src = (sec ? xe : x) + (size_t)pix * Cc;
    float*       dst = (sec ? g_xen : g_xn) + (size_t)pix * Cc;
    const float* w = sec ? ew : nw;
    const float* bb = sec ? eb : nb;

    float4 v = *(const float4*)(src + tid * 4);
    float s  = v.x + v.y + v.z + v.w;
    float ss = v.x*v.x + v.y*v.y + v.z*v.z + v.w*v.w;
    #pragma unroll
    for (int o = 16; o > 0; o >>= 1) {
        s  += __shfl_xor_sync(0xffffffffu, s,  o);
        ss += __shfl_xor_sync(0xffffffffu, ss, o);
    }
    __shared__ float sm[4], sm2[4];
    int wid = tid >> 5;
    if ((tid & 31) == 0) { sm[wid] = s; sm2[wid] = ss; }
    __syncthreads();
    s = sm[0] + sm[1] + sm[2] + sm[3];
    ss = sm2[0] + sm2[1] + sm2[2] + sm2[3];
    float mu = s * (1.0f / Cc);
    float var = ss * (1.0f / Cc) - mu * mu;
    float inv = rsqrtf(var + 1e-6f);
    float4 wv = *(const float4*)(w + tid * 4);
    float4 bv = *(const float4*)(bb + tid * 4);
    float4 o;
    o.x = rnd32((v.x - mu) * inv * wv.x + bv.x);
    o.y = rnd32((v.y - mu) * inv * wv.y + bv.y);
    o.z = rnd32((v.z - mu) * inv * wv.z + bv.z);
    o.w = rnd32((v.w - mu) * inv * wv.w + bv.w);
    *(float4*)(dst + tid * 4) = o;
}

// ===========================================================================
// Pool + mproj
// ===========================================================================
__global__ void pool_kernel()
{
    int blk = blockIdx.x;
    int b = blk / 49, pp = blk % 49;
    int pi = pp / 7, pj = pp % 7;
    int c4 = threadIdx.x * 4;
    const float* src = (c4 < Cc) ? g_xn : g_xen;
    int cc = (c4 < Cc) ? c4 : c4 - Cc;
    float4 s = make_float4(0.f, 0.f, 0.f, 0.f);
    for (int ii = 0; ii < 8; ii++)
        for (int jj = 0; jj < 8; jj++) {
            int pix = b * HW + (pi * 8 + ii) * Ww + (pj * 8 + jj);
            float4 v = *(const float4*)(src + (size_t)pix * Cc + cc);
            s.x += v.x; s.y += v.y; s.z += v.z; s.w += v.w;
        }
    const float inv = 1.0f / 64.0f;
    *(float4*)(g_pool + (size_t)blk * 1024 + c4) =
        make_float4(s.x * inv, s.y * inv, s.z * inv, s.w * inv);
}

__global__ void mproj_kernel(const float* __restrict__ sw, const float* __restrict__ sb)
{
    __shared__ float ps[8 * 1024];
    int r0 = blockIdx.x * 8, tid = threadIdx.x;
    for (int i = tid * 4; i < 8 * 1024; i += 1024)
        *(float4*)&ps[i] = *(const float4*)(g_pool + (size_t)r0 * 1024 + i);
    __syncthreads();
    float acc[8];
    float bias = sb[tid];
    #pragma unroll
    for (int r = 0; r < 8; r++) acc[r] = bias;
    for (int i = 0; i < 1024; i++) {
        float w = sw[(size_t)i * 256 + tid];
        #pragma unroll
        for (int r = 0; r < 8; r++) acc[r] += ps[r * 1024 + i] * w;
    }
    #pragma unroll
    for (int r = 0; r < 8; r++)
        g_m[(size_t)(r0 + r) * 256 + tid] = acc[r];
}

// ===========================================================================
// Fused flash attention: scores + online softmax + PV, 4-way HW split.
// grid (bn=64, cp=4), 256 threads. Dynamic smem.
// smem floats: ms 1568 | ktile 112*33 | vtile 112*33 | sb 49*112 | qmax 49 | qcorr 49
// ===========================================================================
#define ATT_MS    0
#define ATT_KT    1568
#define ATT_VT    (1568 + 3696)
#define ATT_SB    (1568 + 3696 + 3696)
#define ATT_QMAX  (ATT_SB + 5488)
#define ATT_QCORR (ATT_QMAX + 49)
#define SMEM_ATT  ((ATT_QCORR + 49) * 4)

__global__ void __launch_bounds__(256) attn_fused()
{
    extern __shared__ float sm[];
    float* ms    = sm + ATT_MS;
    float* ktile = sm + ATT_KT;
    float* vtile = sm + ATT_VT;
    float* sb    = sm + ATT_SB;
    float* qmax  = sm + ATT_QMAX;
    float* qcorr = sm + ATT_QCORR;

    int bn = blockIdx.x, cp = blockIdx.y;
    int b = bn >> 3, nh = bn & 7;
    int tid = threadIdx.x;
    int d = tid & 31, qg = tid >> 5;
    int kk = tid % 112, half = tid / 112;   // for tid<224
    int q0 = half * 25, q1 = half ? 49 : 25;

    for (int i = tid; i < 49 * 32; i += 256)
        ms[i] = g_m[(size_t)(b * 49 + i / 32) * 256 + nh * 32 + (i & 31)]
                * 0.17677669529663689f;

    float rm = -3.4e38f, rs = 0.f;
    float acc[7] = {0.f, 0.f, 0.f, 0.f, 0.f, 0.f, 0.f};
    int hw0 = cp * 784;

    for (int st = 0; st < 7; st++) {
        __syncthreads();
        // load K/V subtile (112 keys x 32)
        int base = b * HW + hw0 + st * 112;
        for (int u = tid; u < 112 * 8; u += 256) {
            int r = u >> 3, c = u & 7;
            const float* gp = g_kv + (size_t)(base + r) * Cc + nh * 32 + c * 4;
            float4 kv4 = *(const float4*)gp;
            float* dk = &ktile[r * 33 + c * 4];
            dk[0] = kv4.x; dk[1] = kv4.y; dk[2] = kv4.z; dk[3] = kv4.w;
            float4 vv4 = *(const float4*)(gp + C2);
            float* dv = &vtile[r * 33 + c * 4];
            dv[0] = vv4.x; dv[1] = vv4.y; dv[2] = vv4.z; dv[3] = vv4.w;
        }
        __syncthreads();
        // scores
        if (tid < 224) {
            float kr[32];
            #pragma unroll
            for (int j = 0; j < 32; j++) kr[j] = ktile[kk * 33 + j];
            for (int q = q0; q < q1; q++) {
                float s = 0.f;
                #pragma unroll
                for (int j = 0; j < 32; j++) s += ms[q * 32 + j] * kr[j];
                sb[q * 112 + kk] = s;
            }
        }
        __syncthreads();
        // per-query running max + correction
        if (tid < 49) {
            float m = rm;
            #pragma unroll 4
            for (int i = 0; i < 112; i++) m = fmaxf(m, sb[tid * 112 + i]);
            float corr = __expf(rm - m);
            qmax[tid] = m; qcorr[tid] = corr;
            rm = m; rs *= corr;
        }
        __syncthreads();
        // exp
        if (tid < 224) {
            for (int q = q0; q < q1; q++)
                sb[q * 112 + kk] = __expf(sb[q * 112 + kk] - qmax[q]);
        }
        __syncthreads();
        // PV + rowsum
        if (qg < 7) {
            #pragma unroll
            for (int j = 0; j < 7; j++) {
                int q = qg * 7 + j;
                float t = 0.f;
                #pragma unroll 4
                for (int i = 0; i < 112; i++) t += sb[q * 112 + i] * vtile[i * 33 + d];
                acc[j] = acc[j] * qcorr[q] + t;
            }
        }
        if (tid < 49) {
            float s = 0.f;
            #pragma unroll 4
            for (int i = 0; i < 112; i++) s += sb[tid * 112 + i];
            rs += s;
        }
    }

    if (qg < 7) {
        #pragma unroll
        for (int j = 0; j < 7; j++)
            g_a49p[((size_t)(cp * 64 + bn) * 49 + qg * 7 + j) * 32 + d] = acc[j];
    }
    if (tid < 49) {
        g_mpart[(cp * 64 + bn) * 49 + tid] = rm;
        g_spart[(cp * 64 + bn) * 49 + tid] = rs;
    }
}

// merge 4 chunk-partials -> final attn [bn][49][32]
__global__ void attn_merge()
{
    __shared__ float w[4][49];
    int bn = blockIdx.x, tid = threadIdx.x;
    if (tid < 49) {
        float m[4], sgm[4];
        #pragma unroll
        for (int c = 0; c < 4; c++) {
            m[c]  = g_mpart[(c * 64 + bn) * 49 + tid];
            sgm[c] = g_spart[(c * 64 + bn) * 49 + tid];
        }
        float M = fmaxf(fmaxf(m[0], m[1]), fmaxf(m[2], m[3]));
        float e[4], D = 0.f;
        #pragma unroll
        for (int c = 0; c < 4; c++) { e[c] = __expf(m[c] - M); D += sgm[c] * e[c]; }
        float inv = 1.0f / D;
        #pragma unroll
        for (int c = 0; c < 4; c++) w[c][tid] = e[c] * inv;
    }
    __syncthreads();
    for (int u = tid; u < 49 * 32; u += 256) {
        int q = u >> 5, dd = u & 31;
        float v = 0.f;
        #pragma unroll
        for (int c = 0; c < 4; c++)
            v += g_a49p[((size_t)(c * 64 + bn) * 49 + q) * 32 + dd] * w[c][q];
        g_a49[((size_t)bn * 49 + q) * 32 + dd] = v;
    }
}

// ===========================================================================
// Bilinear 7->56 upsample -> xcat[:, 0:256] (tf32-rounded)
// ===========================================================================
__global__ void upsample_kernel()
{
    int p = blockIdx.x;
    int b = p / HW, rem = p % HW;
    int y = rem / Ww, x = rem % Ww;
    int c = threadIdx.x;
    int nh = c >> 5, dd = c & 31;
    int bn = b * NHh + nh;

    float sy = (y + 0.5f) * 0.125f - 0.5f;
    float sx = (x + 0.5f) * 0.125f - 0.5f;
    float fy = floorf(sy), fx = floorf(sx);
    float wy = sy - fy, wx = sx - fx;
    int y0 = max(0, min(6, (int)fy)), y1 = max(0, min(6, (int)fy + 1));
    int x0 = max(0, min(6, (int)fx)), x1 = max(0, min(6, (int)fx + 1));

    const float* A = g_a49 + (size_t)bn * 49 * 32 + dd;
    float s00 = A[(y0 * 7 + x0) * 32];
    float s01 = A[(y0 * 7 + x1) * 32];
    float s10 = A[(y1 * 7 + x0) * 32];
    float s11 = A[(y1 * 7 + x1) * 32];
    float v = (1.f - wy) * ((1.f - wx) * s00 + wx * s01)
            +        wy  * ((1.f - wx) * s10 + wx * s11);
    g_xcat[(size_t)p * Cc + c] = rnd32(v);
}

// ===========================================================================
// Depthwise 7x7 conv (tf32-rounded output)
// ===========================================================================
__global__ void dwconv2(const float* __restrict__ wgt, const float* __restrict__ cb)
{
    __shared__ float tile[196 * 32];
    int sbk = blockIdx.x;
    int b = sbk / 49, t49 = sbk % 49;
    int ty0 = (t49 / 7) * 8, tx0 = (t49 % 7) * 8;
    int cg = blockIdx.y;
    int tid = threadIdx.x;
    int cl = tid & 31, pxg = tid >> 5;
    int ch = cg * 32 + cl;

    for (int u = tid; u < 196 * 8; u += 256) {
        int px = u >> 3, c4 = u & 7;
        int iy = ty0 + px / 14 - 3;
        int ix = tx0 + px % 14 - 3;
        float4 v = make_float4(0.f, 0.f, 0.f, 0.f);
        if (iy >= 0 && iy < Hh && ix >= 0 && ix < Ww)
            v = *(const float4*)(g_e1 + ((size_t)(b * HW) + iy * Ww + ix) * C2 + cg * 32 + c4 * 4);
        *(float4*)&tile[px * 32 + c4 * 4] = v;
    }
    __syncthreads();

    float wr[49];
    #pragma unroll
    for (int i = 0; i < 49; i++) wr[i] = wgt[ch * 49 + i];
    float bias = cb[ch];

    #pragma unroll
    for (int k = 0; k < 8; k++) {
        int o = pxg * 8 + k;
        int oy = o >> 3, ox = o & 7;
        float acc = bias;
        #pragma unroll
        for (int ky = 0; ky < 7; ky++)
            #pragma unroll
            for (int kx = 0; kx < 7; kx++)
                acc += tile[((oy + ky) * 14 + ox + kx) * 32 + cl] * wr[ky * 7 + kx];
        g_e2[((size_t)(b * HW) + (ty0 + oy) * Ww + tx0 + ox) * C2 + ch] = rnd32(acc);
    }
}

// ===========================================================================
// Launch
// ===========================================================================
extern "C" void kernel_launch(void* const* d_in, const int* in_sizes, int n_in,
                              void* d_out, int out_size)
{
    const float* x       = (const float*)d_in[0];
    const float* x_e     = (const float*)d_in[1];
    const float* norm_w  = (const float*)d_in[2];
    const float* norm_b  = (const float*)d_in[3];
    const float* norme_w = (const float*)d_in[4];
    const float* norme_b = (const float*)d_in[5];
    const float* qcut_w  = (const float*)d_in[6];
    const float* qcut_b  = (const float*)d_in[7];
    const float* l_w     = (const float*)d_in[8];
    const float* l_b     = (const float*)d_in[9];
    const float* kv_w    = (const float*)d_in[10];
    const float* kv_b    = (const float*)d_in[11];
    const float* sc_w    = (const float*)d_in[12];
    const float* sc_b    = (const float*)d_in[13];
    const float* efore_w = (const float*)d_in[14];
    const float* efore_b = (const float*)d_in[15];
    const float* econv_w = (const float*)d_in[16];
    const float* econv_b = (const float*)d_in[17];
    const float* eback_w = (const float*)d_in[18];
    const float* eback_b = (const float*)d_in[19];
    const float* proj_w  = (const float*)d_in[20];
    const float* proj_b  = (const float*)d_in[21];
    const float* proje_w = (const float*)d_in[22];
    const float* proje_b = (const float*)d_in[23];
    float* out = (float*)d_out;

    float *xn, *xen, *bfeat, *kv, *xcat, *cut, *e1, *e2, *wt;
    cudaGetSymbolAddress((void**)&xn,    g_xn);
    cudaGetSymbolAddress((void**)&xen,   g_xen);
    cudaGetSymbolAddress((void**)&bfeat, g_bfeat);
    cudaGetSymbolAddress((void**)&kv,    g_kv);
    cudaGetSymbolAddress((void**)&xcat,  g_xcat);
    cudaGetSymbolAddress((void**)&cut,   g_cut);
    cudaGetSymbolAddress((void**)&e1,    g_e1);
    cudaGetSymbolAddress((void**)&e2,    g_e2);
    cudaGetSymbolAddress((void**)&wt,    g_wt);

    cudaFuncSetAttribute((const void*)gemm_mma<0, 0>,
                         cudaFuncAttributeMaxDynamicSharedMemorySize, SMEM_GEMM);
    cudaFuncSetAttribute((const void*)gemm_mma<1, 1>,
                         cudaFuncAttributeMaxDynamicSharedMemorySize, SMEM_GEMM);
    cudaFuncSetAttribute((const void*)gemm_mma<2, 1>,
                         cudaFuncAttributeMaxDynamicSharedMemorySize, SMEM_GEMM);
    cudaFuncSetAttribute((const void*)attn_fused,
                         cudaFuncAttributeMaxDynamicSharedMemorySize, SMEM_ATT);

    // 0. round weights to tf32
    round_tf32_k<<<512, 256>>>(qcut_w,  wt + WT_QCUT,  131072);
    round_tf32_k<<<1024, 256>>>(l_w,    wt + WT_L,     262144);
    round_tf32_k<<<1024, 256>>>(kv_w,   wt + WT_KV,    262144);
    round_tf32_k<<<512, 256>>>(efore_w, wt + WT_EFORE, 131072);
    round_tf32_k<<<256, 256>>>(eback_w, wt + WT_EBACK, 65536);
    round_tf32_k<<<1024, 256>>>(proj_w, wt + WT_PROJ,  262144);
    round_tf32_k<<<1024, 256>>>(proje_w, wt + WT_PROJE, 262144);

    // 1. LayerNorms (tf32-rounded outputs)
    ln_kernel<<<2 * BHW, 128>>>(x, x_e, norm_w, norm_b, norme_w, norme_b);

    // 2-3. pooled queries
    pool_kernel<<<Bn * 49, 256>>>();
    mproj_kernel<<<49, 256>>>(sc_w, sc_b);

    // 4-6. main GEMMs
    gemm_mma<0, 0><<<dim3(2, 196), 256, SMEM_GEMM>>>(xn, wt + WT_QCUT, qcut_b, nullptr,
                                                     cut, 512, 256, 256, 0);
    gemm_mma<1, 1><<<dim3(4, 196), 256, SMEM_GEMM>>>(xn, wt + WT_L, l_b, nullptr,
                                                     bfeat, 512, 512, 512, 0);
    gemm_mma<0, 0><<<dim3(4, 196), 256, SMEM_GEMM>>>(bfeat, wt + WT_KV, kv_b, nullptr,
                                                     kv, 512, 512, 512, 0);

    // 7-8. fused attention + merge
    attn_fused<<<dim3(64, 4), 256, SMEM_ATT>>>();
    attn_merge<<<64, 256>>>();

    // 9. upsample -> xcat[:, 0:256]
    upsample_kernel<<<BHW, 256>>>();

    // 10-12. gating branch
    gemm_mma<0, 0><<<dim3(2, 196), 256, SMEM_GEMM>>>(xen, wt + WT_EFORE, efore_b, nullptr,
                                                     e1, 512, 256, 256, 0);
    dwconv2<<<dim3(392, 8), 256>>>(econv_w, econv_b);
    gemm_mma<2, 1><<<dim3(2, 196), 256, SMEM_GEMM>>>(e2, wt + WT_EBACK, eback_b, cut,
                                                     xcat + 256, 256, 256, 512, 256);

    // 13-14. output projections
    gemm_mma<0, 0><<<dim3(4, 196), 256, SMEM_GEMM>>>(xcat, wt + WT_PROJ, proj_b, nullptr,
                                                     out, 512, 512, 512, 0);
    gemm_mma<0, 0><<<dim3(4, 196), 256, SMEM_GEMM>>>(xcat, wt + WT_PROJE, proje_b, nullptr,
                                                     out + (size_t)BHW * Cc, 512, 512, 512, 0);
}